// round 14
// baseline (speedup 1.0000x reference)
#include <cuda_runtime.h>
#include <float.h>

// ---------------------------------------------------------------------------
// PointSIFT select_cube + group, fused 2-kernel pipeline.
//   k_build: per-batch block; smem histogram + warp-shuffle scan + scatter
//            (counting sort on 10^3 grid, cell size == radius).
//   k_query_gather (R13): sorted-order queries (R12) + SHARED CANDIDATES:
//     the block's 8 spatially-adjacent queries compute their union cell
//     bounds; the union's candidates are cooperatively copied to smem ONCE
//     (warp-per-span), then each warp tests its own query against the smem
//     list with dense 32-lane iterations. Winners via warp-private smem
//     atomicMin on 64-bit (dist_bits<<32 | j) keys (exact reference
//     semantics: unfused fp32 dist, min-dist then min-j; the coordinate
//     test |d|<r filters any union-extra candidates, so results are
//     identical). Oversized unions (grid wrap) take a per-warp LDG fallback.
//     Gather: warp q owns query q; float4 loads staged in smem, written out
//     as aligned float4 stores to the query's original row.
//
// Output layout (float32, reference return order):
//   [0 .. BN*8*3)             grouped_xyz   [B,N,8,3]
//   [.. +BN*8*(3+C))          grouped_points[B,N,8,3+C]
//   [.. +BN*8)                idx (int32 cast to float) [B,N,8]
// ---------------------------------------------------------------------------

#define GRIDR    10
#define NCELL    (GRIDR*GRIDR*GRIDR)  // 1000
#define BMAX     2
#define NMAX     4096
#define PRADIUS  0.1f
#define QPB      8                    // queries per block == warps per block
#define CFEAT    64
#define FROW     (3 + CFEAT)          // 67
#define GPROW    (8 * FROW)           // 536 floats per query row
#define CAND_MAX 448
#define SPAN_MAX 32

__device__ int    g_start [BMAX * (NCELL + 1)];
__device__ float4 g_sorted[BMAX * NMAX];   // x,y,z, w = bitcast(orig index)

__device__ __forceinline__ int cell_of(float x, float y, float z) {
    int cx = (int)(x * 10.0f); cx = min(max(cx, 0), GRIDR - 1);
    int cy = (int)(y * 10.0f); cy = min(max(cy, 0), GRIDR - 1);
    int cz = (int)(z * 10.0f); cz = min(max(cz, 0), GRIDR - 1);
    return (cx * GRIDR + cy) * GRIDR + cz;
}

// One block per batch. Histogram + warp-shuffle scan + scatter via smem.
__global__ __launch_bounds__(1024) void k_build(const float* __restrict__ xyz,
                                                int N) {
    __shared__ int s_cur [NCELL];
    __shared__ int s_wsum[32];

    int b   = blockIdx.x;
    int tid = threadIdx.x;
    int wid = tid >> 5;
    int lid = tid & 31;
    const float* xb = xyz + (size_t)b * N * 3;

    if (tid < NCELL) s_cur[tid] = 0;
    __syncthreads();

    const int PT = (NMAX + 1023) / 1024;   // 4
    float px[PT], py[PT], pz[PT];
    int   pc[PT];
    #pragma unroll
    for (int p = 0; p < PT; p++) {
        int i = tid + p * 1024;
        pc[p] = -1;
        if (i < N) {
            px[p] = xb[3 * i + 0];
            py[p] = xb[3 * i + 1];
            pz[p] = xb[3 * i + 2];
            pc[p] = cell_of(px[p], py[p], pz[p]);
            atomicAdd(&s_cur[pc[p]], 1);
        }
    }
    __syncthreads();

    int v = (tid < NCELL) ? s_cur[tid] : 0;
    int x = v;
    #pragma unroll
    for (int off = 1; off < 32; off <<= 1) {
        int y = __shfl_up_sync(0xFFFFFFFFu, x, off);
        if (lid >= off) x += y;
    }
    if (lid == 31) s_wsum[wid] = x;
    __syncthreads();
    if (wid == 0) {
        int y = s_wsum[lid];
        #pragma unroll
        for (int off = 1; off < 32; off <<= 1) {
            int z2 = __shfl_up_sync(0xFFFFFFFFu, y, off);
            if (lid >= off) y += z2;
        }
        s_wsum[lid] = y;
    }
    __syncthreads();
    int incl = x + (wid > 0 ? s_wsum[wid - 1] : 0);
    if (tid < NCELL) {
        int excl = incl - v;
        g_start[b * (NCELL + 1) + tid] = excl;
        s_cur[tid] = excl;
        if (tid == NCELL - 1)
            g_start[b * (NCELL + 1) + NCELL] = incl;
    }
    __syncthreads();

    float4* dst = g_sorted + (size_t)b * NMAX;
    #pragma unroll
    for (int p = 0; p < PT; p++) {
        if (pc[p] >= 0) {
            int pos = atomicAdd(&s_cur[pc[p]], 1);
            int i = tid + p * 1024;
            dst[pos] = make_float4(px[p], py[p], pz[p], __int_as_float(i));
        }
    }
}

// 8 sorted-order queries/block; shared smem candidate list; warp-per-query.
__global__ __launch_bounds__(QPB * 32)
void k_query_gather(const float* __restrict__ xyz,
                    const float* __restrict__ pts,
                    float* __restrict__ gxyz,
                    float* __restrict__ gp,
                    float* __restrict__ idx_f,
                    int B, int N) {
    __shared__ alignas(16) float4 s_cand[CAND_MAX];
    __shared__ alignas(16) float  s_stage[QPB][GPROW];
    __shared__ alignas(16) float  s_gx   [QPB][24];
    __shared__ unsigned long long s_key  [QPB][8];
    __shared__ int                s_jj   [QPB][8];
    __shared__ int s_excl[SPAN_MAX + 1];
    __shared__ int s_src [SPAN_MAX];
    __shared__ int s_ub  [6];          // ux0,ux1,uy0,uy1,uz0,uz1
    __shared__ int s_ctl [2];          // total, fallback

    const int tid  = threadIdx.x;
    const int w    = tid >> 5;
    const int lane = tid & 31;

    const int bpb = N / QPB;               // blocks per batch (512)
    const int b   = blockIdx.x / bpb;
    const int q0  = (blockIdx.x - b * bpb) * QPB;

    const float* xb = xyz + (size_t)b * N * 3;
    const float4* __restrict__ srt = g_sorted + (size_t)b * NMAX;
    const int sbase = b * (NCELL + 1);

    if (tid < 2) s_ctl[tid] = 0;
    if (tid < 6) s_ub[tid] = (tid & 1) ? -1 : GRIDR;
    __syncthreads();

    // ---- per-query cell ranges + union bounds ----
    const float4 sq = srt[q0 + w];
    const float xi = sq.x, yi = sq.y, zi = sq.z;

    int cx = min(max((int)(xi * 10.0f), 0), GRIDR - 1);
    int cy = min(max((int)(yi * 10.0f), 0), GRIDR - 1);
    int cz = min(max((int)(zi * 10.0f), 0), GRIDR - 1);
    int ax0 = max(cx - 1, 0), ax1 = min(cx + 1, GRIDR - 1);
    int ay0 = max(cy - 1, 0), ay1 = min(cy + 1, GRIDR - 1);
    int az0 = max(cz - 1, 0), az1 = min(cz + 1, GRIDR - 1);

    if (lane == 0) {
        atomicMin(&s_ub[0], ax0); atomicMax(&s_ub[1], ax1);
        atomicMin(&s_ub[2], ay0); atomicMax(&s_ub[3], ay1);
        atomicMin(&s_ub[4], az0); atomicMax(&s_ub[5], az1);
    }
    // seed own winner keys: (FLT_MAX, original self index)
    if (lane < 8)
        s_key[w][lane] = ((unsigned long long)0x7F7FFFFFull << 32)
                       | (unsigned)__float_as_int(sq.w);
    __syncthreads();

    // ---- warp 0: build union span table ----
    if (w == 0) {
        int ux0 = s_ub[0], ux1 = s_ub[1];
        int uy0 = s_ub[2], uy1 = s_ub[3];
        int uz0 = s_ub[4], uz1 = s_ub[5];
        int uny = uy1 - uy0 + 1;
        int nspan = (ux1 - ux0 + 1) * uny;

        int rs = 0, re = 0;
        if (nspan <= SPAN_MAX && lane < nspan) {
            int dxy = lane / uny;
            int rowc = ((ux0 + dxy) * GRIDR + (uy0 + lane - dxy * uny)) * GRIDR;
            rs = g_start[sbase + rowc + uz0];
            re = g_start[sbase + rowc + uz1 + 1];
        }
        int sz = re - rs;
        int inc = sz;
        #pragma unroll
        for (int off = 1; off < 32; off <<= 1) {
            int t = __shfl_up_sync(0xFFFFFFFFu, inc, off);
            if (lane >= off) inc += t;
        }
        int total = __shfl_sync(0xFFFFFFFFu, inc,
                                (nspan <= SPAN_MAX ? nspan : SPAN_MAX) - 1);
        if (nspan > SPAN_MAX || total > CAND_MAX) {
            if (lane == 0) s_ctl[1] = 1;
        } else {
            if (lane < nspan) { s_excl[lane] = inc - sz; s_src[lane] = rs; }
            if (lane == 0) {
                s_excl[nspan] = total;
                s_ctl[0] = (nspan << 16) | total;
            }
        }
    }
    __syncthreads();

    const int fallback = s_ctl[1];

    if (!fallback) {
        const int packed = s_ctl[0];
        const int total  = packed & 0xFFFF;
        const int nspan  = packed >> 16;

        // cooperative copy, warp-per-span (no per-candidate span select)
        for (int sp = w; sp < nspan; sp += QPB) {
            int dst = s_excl[sp];
            int cnt = s_excl[sp + 1] - dst;
            int src = s_src[sp];
            for (int k = lane; k < cnt; k += 32)
                s_cand[dst + k] = srt[src + k];
        }
        __syncthreads();

        // dense warp-per-query search over smem candidates
        for (int c = lane; c < total; c += 32) {
            float4 p = s_cand[c];
            float dx = p.x - xi;
            float dy = p.y - yi;
            float dz = p.z - zi;
            if ((fabsf(dx) < PRADIUS) & (fabsf(dy) < PRADIUS) &
                (fabsf(dz) < PRADIUS)) {
                unsigned j = (unsigned)__float_as_int(p.w);
                float d = __fadd_rn(
                    __fadd_rn(__fmul_rn(dx, dx), __fmul_rn(dy, dy)),
                    __fmul_rn(dz, dz));
                unsigned long long ck =
                    ((unsigned long long)(unsigned)__float_as_int(d) << 32) | j;
                int oct = ((dx > 0.0f) ? 4 : 0) |
                          ((dy > 0.0f) ? 2 : 0) |
                          ((dz > 0.0f) ? 1 : 0);
                atomicMin(&s_key[w][oct], ck);
            }
        }
    } else {
        // rare: per-warp LDG search over own 27-cell spans
        int ny = ay1 - ay0 + 1;
        int ns = (ax1 - ax0 + 1) * ny;
        for (int sp = 0; sp < ns; sp++) {
            int dxy = sp / ny;
            int rowc = ((ax0 + dxy) * GRIDR + (ay0 + sp - dxy * ny)) * GRIDR;
            int s0 = g_start[sbase + rowc + az0];
            int e0 = g_start[sbase + rowc + az1 + 1];
            for (int k = s0 + lane; k < e0; k += 32) {
                float4 p = srt[k];
                float dx = p.x - xi;
                float dy = p.y - yi;
                float dz = p.z - zi;
                if ((fabsf(dx) < PRADIUS) & (fabsf(dy) < PRADIUS) &
                    (fabsf(dz) < PRADIUS)) {
                    unsigned j = (unsigned)__float_as_int(p.w);
                    float d = __fadd_rn(
                        __fadd_rn(__fmul_rn(dx, dx), __fmul_rn(dy, dy)),
                        __fmul_rn(dz, dz));
                    unsigned long long ck =
                        ((unsigned long long)(unsigned)__float_as_int(d) << 32) | j;
                    int oct = ((dx > 0.0f) ? 4 : 0) |
                              ((dy > 0.0f) ? 2 : 0) |
                              ((dz > 0.0f) ? 1 : 0);
                    atomicMin(&s_key[w][oct], ck);
                }
            }
        }
    }
    __syncwarp();

    // ---- publish winners (warp-private) + gather ----
    const int iw  = __float_as_int(sq.w);        // original index -> out row
    const size_t row = (size_t)b * N + iw;

    if (lane < 8) {
        int j = (int)(unsigned)(s_key[w][lane] & 0xFFFFFFFFull);
        s_jj[w][lane] = j;
        idx_f[row * 8 + lane] = (float)j;
    }
    __syncwarp();

    // centered xyz: 24 values (lanes 0..23)
    if (lane < 24) {
        int o = lane / 3;
        int c = lane - o * 3;
        int jj = s_jj[w][o];
        float own = (c == 0) ? sq.x : (c == 1) ? sq.y : sq.z;
        float v = xb[3 * jj + c] - own;
        s_stage[w][o * FROW + c] = v;
        s_gx[w][lane] = v;
    }

    // features: 8 octants x 16 float4 = 128 vector loads, 4 dense iterations
    const float4* __restrict__ pb4 =
        (const float4*)(pts + (size_t)b * N * CFEAT);
    #pragma unroll
    for (int t0 = 0; t0 < 4; t0++) {
        int t  = lane + t0 * 32;     // 0..127
        int o  = t >> 4;
        int q  = t & 15;
        int jj = s_jj[w][o];
        float4 f4 = pb4[(size_t)jj * 16 + q];
        int base = o * FROW + 3 + q * 4;
        s_stage[w][base + 0] = f4.x;
        s_stage[w][base + 1] = f4.y;
        s_stage[w][base + 2] = f4.z;
        s_stage[w][base + 3] = f4.w;
    }
    __syncwarp();

    // write-out: 536 floats = 134 aligned float4 to the original row
    float4*       gpo = (float4*)(gp + row * GPROW);
    const float4* st4 = (const float4*)s_stage[w];
    #pragma unroll
    for (int f = lane; f < GPROW / 4; f += 32)
        gpo[f] = st4[f];
    if (lane < 6)
        ((float4*)(gxyz + row * 24))[lane] =
            ((const float4*)s_gx[w])[lane];
}

extern "C" void kernel_launch(void* const* d_in, const int* in_sizes, int n_in,
                              void* d_out, int out_size) {
    const float* xyz = (const float*)d_in[0];
    const float* pts = (const float*)d_in[1];
    float* out = (float*)d_out;

    int BN = in_sizes[0] / 3;       // B*N = 8192
    int B  = 2;
    int N  = BN / B;                // 4096

    size_t nG = (size_t)BN * 8;
    float* gxyz  = out;
    float* gp    = out + nG * 3;
    float* idx_f = out + nG * 3 + nG * (size_t)FROW;

    k_build<<<B, 1024>>>(xyz, N);
    k_query_gather<<<(BN + QPB - 1) / QPB, QPB * 32>>>(
        xyz, pts, gxyz, gp, idx_f, B, N);
}

// round 15
// speedup vs baseline: 1.0917x; 1.0917x over previous
#include <cuda_runtime.h>
#include <float.h>

// ---------------------------------------------------------------------------
// PointSIFT select_cube + group, fused 2-kernel pipeline (R12 kernels + PDL).
//   k_build: per-batch block; smem histogram + warp-shuffle scan + scatter
//            (counting sort on 10^3 grid, cell size == radius). Fires
//            griddepcontrol.launch_dependents at entry so the query grid is
//            placed on the idle SMs and waits in hardware.
//   k_query_gather (R12): queries processed in CELL-SORTED order — block's 8
//     queries come from consecutive g_sorted slots, so all 16 strips of a
//     block touch (nearly) the same 27-cell neighborhood -> candidate loads
//     hit L1. Original index rides in .w for output addressing.
//     Search: 2 strips x 16 lanes per query (z-spans split by parity),
//       winners via block-smem atomicMin on 64-bit (dist_bits<<32 | j) keys
//       (exact reference semantics: unfused fp32 dist, min-dist then min-j).
//     Gather: warp q owns query q; float4 feature loads staged in smem,
//       write-out as aligned float4 stores to the query's original row.
//     Starts with griddepcontrol.wait (PDL) before touching build output.
//
// Output layout (float32, reference return order):
//   [0 .. BN*8*3)             grouped_xyz   [B,N,8,3]
//   [.. +BN*8*(3+C))          grouped_points[B,N,8,3+C]
//   [.. +BN*8)                idx (int32 cast to float) [B,N,8]
// ---------------------------------------------------------------------------

#define GRIDR   10
#define NCELL   (GRIDR*GRIDR*GRIDR)   // 1000
#define BMAX    2
#define NMAX    4096
#define PRADIUS 0.1f
#define QPB     8                     // queries per block == warps per block
#define CFEAT   64
#define FROW    (3 + CFEAT)           // 67
#define GPROW   (8 * FROW)            // 536 floats per query row

__device__ int    g_start [BMAX * (NCELL + 1)];
__device__ float4 g_sorted[BMAX * NMAX];   // x,y,z, w = bitcast(orig index)

__device__ __forceinline__ int cell_of(float x, float y, float z) {
    int cx = (int)(x * 10.0f); cx = min(max(cx, 0), GRIDR - 1);
    int cy = (int)(y * 10.0f); cy = min(max(cy, 0), GRIDR - 1);
    int cz = (int)(z * 10.0f); cz = min(max(cz, 0), GRIDR - 1);
    return (cx * GRIDR + cy) * GRIDR + cz;
}

// One block per batch. Histogram + warp-shuffle scan + scatter via smem.
__global__ __launch_bounds__(1024) void k_build(const float* __restrict__ xyz,
                                                int N) {
    // PDL: let the dependent (query) grid launch & park on idle SMs now.
    asm volatile("griddepcontrol.launch_dependents;");

    __shared__ int s_cur [NCELL];
    __shared__ int s_wsum[32];

    int b   = blockIdx.x;
    int tid = threadIdx.x;
    int wid = tid >> 5;
    int lid = tid & 31;
    const float* xb = xyz + (size_t)b * N * 3;

    if (tid < NCELL) s_cur[tid] = 0;
    __syncthreads();

    const int PT = (NMAX + 1023) / 1024;   // 4
    float px[PT], py[PT], pz[PT];
    int   pc[PT];
    #pragma unroll
    for (int p = 0; p < PT; p++) {
        int i = tid + p * 1024;
        pc[p] = -1;
        if (i < N) {
            px[p] = xb[3 * i + 0];
            py[p] = xb[3 * i + 1];
            pz[p] = xb[3 * i + 2];
            pc[p] = cell_of(px[p], py[p], pz[p]);
            atomicAdd(&s_cur[pc[p]], 1);
        }
    }
    __syncthreads();

    int v = (tid < NCELL) ? s_cur[tid] : 0;
    int x = v;
    #pragma unroll
    for (int off = 1; off < 32; off <<= 1) {
        int y = __shfl_up_sync(0xFFFFFFFFu, x, off);
        if (lid >= off) x += y;
    }
    if (lid == 31) s_wsum[wid] = x;
    __syncthreads();
    if (wid == 0) {
        int y = s_wsum[lid];
        #pragma unroll
        for (int off = 1; off < 32; off <<= 1) {
            int z2 = __shfl_up_sync(0xFFFFFFFFu, y, off);
            if (lid >= off) y += z2;
        }
        s_wsum[lid] = y;
    }
    __syncthreads();
    int incl = x + (wid > 0 ? s_wsum[wid - 1] : 0);
    if (tid < NCELL) {
        int excl = incl - v;
        g_start[b * (NCELL + 1) + tid] = excl;
        s_cur[tid] = excl;
        if (tid == NCELL - 1)
            g_start[b * (NCELL + 1) + NCELL] = incl;
    }
    __syncthreads();

    float4* dst = g_sorted + (size_t)b * NMAX;
    #pragma unroll
    for (int p = 0; p < PT; p++) {
        if (pc[p] >= 0) {
            int pos = atomicAdd(&s_cur[pc[p]], 1);
            int i = tid + p * 1024;
            dst[pos] = make_float4(px[p], py[p], pz[p], __int_as_float(i));
        }
    }
}

// 8 sorted-order queries/block; 2 strips x 16 lanes per query.
__global__ __launch_bounds__(QPB * 32)
void k_query_gather(const float* __restrict__ xyz,
                    const float* __restrict__ pts,
                    float* __restrict__ gxyz,
                    float* __restrict__ gp,
                    float* __restrict__ idx_f,
                    int B, int N) {
    __shared__ unsigned long long s_key [QPB][8];
    __shared__ int                s_jj  [QPB][8];
    __shared__ alignas(16) float  s_stage[QPB][GPROW];  // 8 x 536
    __shared__ alignas(16) float  s_gx   [QPB][24];

    const int tid    = threadIdx.x;
    const int w      = tid >> 5;
    const int lane   = tid & 31;
    const int h      = lane >> 4;          // half-warp id
    const int lane16 = lane & 15;
    const int strip  = w & 1;              // span-parity strip
    const int qb     = (w & ~1) + h;       // query slot in block (0..7)

    const int bpb = N / QPB;               // blocks per batch (512)
    const int b   = blockIdx.x / bpb;
    const int q0  = (blockIdx.x - b * bpb) * QPB;  // sorted-array offset

    // PDL: wait for k_build's writes (no-op when serialized normally).
    asm volatile("griddepcontrol.wait;" ::: "memory");

    const float* xb = xyz + (size_t)b * N * 3;
    const float4* __restrict__ srt = g_sorted + (size_t)b * NMAX;

    // seed winner keys: (FLT_MAX, original self index)
    if (tid < QPB * 8) {
        int q  = tid >> 3;
        int iq = __float_as_int(srt[q0 + q].w);
        s_key[q][tid & 7] =
            ((unsigned long long)0x7F7FFFFFull << 32) | (unsigned)iq;
    }
    __syncthreads();

    // ---------------- search (query slot qb, sorted order) ----------------
    const float4 sq = srt[q0 + qb];
    const float xi = sq.x, yi = sq.y, zi = sq.z;

    int cx = min(max((int)(xi * 10.0f), 0), GRIDR - 1);
    int cy = min(max((int)(yi * 10.0f), 0), GRIDR - 1);
    int cz = min(max((int)(zi * 10.0f), 0), GRIDR - 1);
    int ax0 = max(cx - 1, 0), ax1 = min(cx + 1, GRIDR - 1);
    int ay0 = max(cy - 1, 0), ay1 = min(cy + 1, GRIDR - 1);
    int az0 = max(cz - 1, 0), az1 = min(cz + 1, GRIDR - 1);
    int ny = ay1 - ay0 + 1;
    int ns = (ax1 - ax0 + 1) * ny;         // 4..9 spans

    const unsigned hm = 0xFFFFu << (h * 16);
    const int sbase = b * (NCELL + 1);

    // prefetch all span ranges in parallel (lanes 0..ns-1 of this half)
    int rs = 0, re = 0;
    if (lane16 < ns) {
        int dxy = lane16 / ny;
        int rowc = ((ax0 + dxy) * GRIDR + (ay0 + lane16 - dxy * ny)) * GRIDR;
        rs = g_start[sbase + rowc + az0];
        re = g_start[sbase + rowc + az1 + 1];
    }

    for (int sp = strip; sp < ns; sp += 2) {
        int s0 = __shfl_sync(hm, rs, sp, 16);
        int e0 = __shfl_sync(hm, re, sp, 16);
        for (int k = s0 + lane16; k < e0; k += 16) {
            float4 p = srt[k];
            float dx = p.x - xi;
            float dy = p.y - yi;
            float dz = p.z - zi;
            if ((fabsf(dx) < PRADIUS) & (fabsf(dy) < PRADIUS) &
                (fabsf(dz) < PRADIUS)) {
                unsigned j = (unsigned)__float_as_int(p.w);
                float d = __fadd_rn(
                    __fadd_rn(__fmul_rn(dx, dx), __fmul_rn(dy, dy)),
                    __fmul_rn(dz, dz));
                unsigned long long ck =
                    ((unsigned long long)(unsigned)__float_as_int(d) << 32) | j;
                int oct = ((dx > 0.0f) ? 4 : 0) |
                          ((dy > 0.0f) ? 2 : 0) |
                          ((dz > 0.0f) ? 1 : 0);
                atomicMin(&s_key[qb][oct], ck);
            }
        }
    }
    __syncthreads();

    // publish winners into s_jj (idx written per-query below)
    if (tid < QPB * 8) {
        s_jj[tid >> 3][tid & 7] =
            (int)(unsigned)(s_key[tid >> 3][tid & 7] & 0xFFFFFFFFull);
    }
    __syncthreads();

    // ---------------- gather: warp w owns sorted query (q0 + w) -----------
    const float4 mq = srt[q0 + w];
    const int    iw = __float_as_int(mq.w);      // original index -> out row
    const size_t row = (size_t)b * N + iw;

    if (lane < 8)
        idx_f[row * 8 + lane] = (float)s_jj[w][lane];

    // centered xyz: 24 values (lanes 0..23)
    if (lane < 24) {
        int o = lane / 3;
        int c = lane - o * 3;
        int jj = s_jj[w][o];
        float own = (c == 0) ? mq.x : (c == 1) ? mq.y : mq.z;
        float v = xb[3 * jj + c] - own;
        s_stage[w][o * FROW + c] = v;
        s_gx[w][lane] = v;
    }

    // features: 8 octants x 16 float4 = 128 vector loads, 4 dense iterations
    const float4* __restrict__ pb4 =
        (const float4*)(pts + (size_t)b * N * CFEAT);
    #pragma unroll
    for (int t0 = 0; t0 < 4; t0++) {
        int t  = lane + t0 * 32;     // 0..127
        int o  = t >> 4;
        int q  = t & 15;
        int jj = s_jj[w][o];
        float4 f4 = pb4[(size_t)jj * 16 + q];
        int base = o * FROW + 3 + q * 4;
        s_stage[w][base + 0] = f4.x;
        s_stage[w][base + 1] = f4.y;
        s_stage[w][base + 2] = f4.z;
        s_stage[w][base + 3] = f4.w;
    }
    __syncwarp();

    // write-out: 536 floats = 134 aligned float4 to the original row
    float4*       gpo = (float4*)(gp + row * GPROW);
    const float4* st4 = (const float4*)s_stage[w];
    #pragma unroll
    for (int f = lane; f < GPROW / 4; f += 32)
        gpo[f] = st4[f];
    if (lane < 6)
        ((float4*)(gxyz + row * 24))[lane] =
            ((const float4*)s_gx[w])[lane];
}

extern "C" void kernel_launch(void* const* d_in, const int* in_sizes, int n_in,
                              void* d_out, int out_size) {
    const float* xyz = (const float*)d_in[0];
    const float* pts = (const float*)d_in[1];
    float* out = (float*)d_out;

    int BN = in_sizes[0] / 3;       // B*N = 8192
    int B  = 2;
    int N  = BN / B;                // 4096

    size_t nG = (size_t)BN * 8;
    float* gxyz  = out;
    float* gp    = out + nG * 3;
    float* idx_f = out + nG * 3 + nG * (size_t)FROW;

    k_build<<<B, 1024>>>((const float*)xyz, N);

    // PDL launch of the dependent query kernel on the same (capture) stream.
    {
        cudaLaunchAttribute attrs[1];
        attrs[0].id = cudaLaunchAttributeProgrammaticStreamSerialization;
        attrs[0].val.programmaticStreamSerializationAllowed = 1;

        cudaLaunchConfig_t cfg = {};
        cfg.gridDim  = dim3((BN + QPB - 1) / QPB, 1, 1);
        cfg.blockDim = dim3(QPB * 32, 1, 1);
        cfg.dynamicSmemBytes = 0;
        cfg.stream = 0;                 // legacy default stream (captured)
        cfg.attrs = attrs;
        cfg.numAttrs = 1;

        float* gxyz_p  = gxyz;
        float* gp_p    = gp;
        float* idx_p   = idx_f;
        cudaLaunchKernelEx(&cfg, k_query_gather,
                           xyz, pts, gxyz_p, gp_p, idx_p, B, N);
    }
}

// round 16
// speedup vs baseline: 1.1064x; 1.0135x over previous
#include <cuda_runtime.h>
#include <float.h>

// ---------------------------------------------------------------------------
// PointSIFT select_cube + group, fused 2-kernel pipeline (R12 kernels + PDL).
//   k_build: per-batch block; smem histogram + warp-shuffle scan + scatter
//            (counting sort on 10^3 grid, cell size == radius).
//   k_query_gather: sorted-order queries; 2 strips x 16 lanes per query.
//     R15b: span loop is SOFTWARE-PIPELINED (depth 2) — span t+1's range
//     shuffle + candidate LDG issue before span t is tested, halving the
//     exposed shfl->LDG dependent-chain latency. Within-cube test via
//     max(|dx|,|dy|,|dz|) < r (exactly equivalent). Winners via block-smem
//     atomicMin on 64-bit (dist_bits<<32 | j) keys (exact reference
//     semantics: unfused fp32 dist, min-dist then min-j tie-break).
//     Gather: warp q owns query q; float4 loads staged in smem, written out
//     as aligned float4 stores to the query's original row.
//
// Output layout (float32, reference return order):
//   [0 .. BN*8*3)             grouped_xyz   [B,N,8,3]
//   [.. +BN*8*(3+C))          grouped_points[B,N,8,3+C]
//   [.. +BN*8)                idx (int32 cast to float) [B,N,8]
// ---------------------------------------------------------------------------

#define GRIDR   10
#define NCELL   (GRIDR*GRIDR*GRIDR)   // 1000
#define BMAX    2
#define NMAX    4096
#define PRADIUS 0.1f
#define QPB     8                     // queries per block == warps per block
#define CFEAT   64
#define FROW    (3 + CFEAT)           // 67
#define GPROW   (8 * FROW)            // 536 floats per query row

__device__ int    g_start [BMAX * (NCELL + 1)];
__device__ float4 g_sorted[BMAX * NMAX];   // x,y,z, w = bitcast(orig index)

__device__ __forceinline__ int cell_of(float x, float y, float z) {
    int cx = (int)(x * 10.0f); cx = min(max(cx, 0), GRIDR - 1);
    int cy = (int)(y * 10.0f); cy = min(max(cy, 0), GRIDR - 1);
    int cz = (int)(z * 10.0f); cz = min(max(cz, 0), GRIDR - 1);
    return (cx * GRIDR + cy) * GRIDR + cz;
}

// One block per batch. Histogram + warp-shuffle scan + scatter via smem.
__global__ __launch_bounds__(1024) void k_build(const float* __restrict__ xyz,
                                                int N) {
    asm volatile("griddepcontrol.launch_dependents;");

    __shared__ int s_cur [NCELL];
    __shared__ int s_wsum[32];

    int b   = blockIdx.x;
    int tid = threadIdx.x;
    int wid = tid >> 5;
    int lid = tid & 31;
    const float* xb = xyz + (size_t)b * N * 3;

    if (tid < NCELL) s_cur[tid] = 0;
    __syncthreads();

    const int PT = (NMAX + 1023) / 1024;   // 4
    float px[PT], py[PT], pz[PT];
    int   pc[PT];
    #pragma unroll
    for (int p = 0; p < PT; p++) {
        int i = tid + p * 1024;
        pc[p] = -1;
        if (i < N) {
            px[p] = xb[3 * i + 0];
            py[p] = xb[3 * i + 1];
            pz[p] = xb[3 * i + 2];
            pc[p] = cell_of(px[p], py[p], pz[p]);
            atomicAdd(&s_cur[pc[p]], 1);
        }
    }
    __syncthreads();

    int v = (tid < NCELL) ? s_cur[tid] : 0;
    int x = v;
    #pragma unroll
    for (int off = 1; off < 32; off <<= 1) {
        int y = __shfl_up_sync(0xFFFFFFFFu, x, off);
        if (lid >= off) x += y;
    }
    if (lid == 31) s_wsum[wid] = x;
    __syncthreads();
    if (wid == 0) {
        int y = s_wsum[lid];
        #pragma unroll
        for (int off = 1; off < 32; off <<= 1) {
            int z2 = __shfl_up_sync(0xFFFFFFFFu, y, off);
            if (lid >= off) y += z2;
        }
        s_wsum[lid] = y;
    }
    __syncthreads();
    int incl = x + (wid > 0 ? s_wsum[wid - 1] : 0);
    if (tid < NCELL) {
        int excl = incl - v;
        g_start[b * (NCELL + 1) + tid] = excl;
        s_cur[tid] = excl;
        if (tid == NCELL - 1)
            g_start[b * (NCELL + 1) + NCELL] = incl;
    }
    __syncthreads();

    float4* dst = g_sorted + (size_t)b * NMAX;
    #pragma unroll
    for (int p = 0; p < PT; p++) {
        if (pc[p] >= 0) {
            int pos = atomicAdd(&s_cur[pc[p]], 1);
            int i = tid + p * 1024;
            dst[pos] = make_float4(px[p], py[p], pz[p], __int_as_float(i));
        }
    }
}

// 8 sorted-order queries/block; 2 strips x 16 lanes; pipelined span loop.
__global__ __launch_bounds__(QPB * 32)
void k_query_gather(const float* __restrict__ xyz,
                    const float* __restrict__ pts,
                    float* __restrict__ gxyz,
                    float* __restrict__ gp,
                    float* __restrict__ idx_f,
                    int B, int N) {
    __shared__ unsigned long long s_key [QPB][8];
    __shared__ int                s_jj  [QPB][8];
    __shared__ alignas(16) float  s_stage[QPB][GPROW];  // 8 x 536
    __shared__ alignas(16) float  s_gx   [QPB][24];

    const int tid    = threadIdx.x;
    const int w      = tid >> 5;
    const int lane   = tid & 31;
    const int h      = lane >> 4;          // half-warp id
    const int lane16 = lane & 15;
    const int strip  = w & 1;              // span-parity strip
    const int qb     = (w & ~1) + h;       // query slot in block (0..7)

    const int bpb = N / QPB;               // blocks per batch (512)
    const int b   = blockIdx.x / bpb;
    const int q0  = (blockIdx.x - b * bpb) * QPB;  // sorted-array offset

    asm volatile("griddepcontrol.wait;" ::: "memory");

    const float* xb = xyz + (size_t)b * N * 3;
    const float4* __restrict__ srt = g_sorted + (size_t)b * NMAX;

    // seed winner keys: (FLT_MAX, original self index)
    if (tid < QPB * 8) {
        int q  = tid >> 3;
        int iq = __float_as_int(srt[q0 + q].w);
        s_key[q][tid & 7] =
            ((unsigned long long)0x7F7FFFFFull << 32) | (unsigned)iq;
    }
    __syncthreads();

    // ---------------- search (query slot qb, sorted order) ----------------
    const float4 sq = srt[q0 + qb];
    const float xi = sq.x, yi = sq.y, zi = sq.z;

    int cx = min(max((int)(xi * 10.0f), 0), GRIDR - 1);
    int cy = min(max((int)(yi * 10.0f), 0), GRIDR - 1);
    int cz = min(max((int)(zi * 10.0f), 0), GRIDR - 1);
    int ax0 = max(cx - 1, 0), ax1 = min(cx + 1, GRIDR - 1);
    int ay0 = max(cy - 1, 0), ay1 = min(cy + 1, GRIDR - 1);
    int az0 = max(cz - 1, 0), az1 = min(cz + 1, GRIDR - 1);
    int ny = ay1 - ay0 + 1;
    int ns = (ax1 - ax0 + 1) * ny;         // 4..9 spans

    const unsigned hm = 0xFFFFu << (h * 16);
    const int sbase = b * (NCELL + 1);

    // prefetch all span ranges in parallel (lanes 0..ns-1 of this half)
    int rs = 0, re = 0;
    if (lane16 < ns) {
        int dxy = lane16 / ny;
        int rowc = ((ax0 + dxy) * GRIDR + (ay0 + lane16 - dxy * ny)) * GRIDR;
        rs = g_start[sbase + rowc + az0];
        re = g_start[sbase + rowc + az1 + 1];
    }

    // ---- depth-2 software-pipelined span loop (this strip: sp += 2) ----
    {
        int   sp    = strip;
        int   kcur  = 0, ecur = 0;
        bool  vcur  = false;
        float4 pcur;
        if (sp < ns) {
            int s0 = __shfl_sync(hm, rs, sp, 16);
            ecur   = __shfl_sync(hm, re, sp, 16);
            kcur   = s0 + lane16;
            vcur   = kcur < ecur;
            if (vcur) pcur = srt[kcur];
        }
        while (sp < ns) {
            // prefetch next span (range shuffle + candidate load) NOW
            int   spn  = sp + 2;
            int   knxt = 0, enxt = 0;
            bool  vnxt = false;
            float4 pnxt;
            if (spn < ns) {
                int s1 = __shfl_sync(hm, rs, spn, 16);
                enxt   = __shfl_sync(hm, re, spn, 16);
                knxt   = s1 + lane16;
                vnxt   = knxt < enxt;
                if (vnxt) pnxt = srt[knxt];
            }

            // process current span's first 16 lanes
            if (vcur) {
                float dx = pcur.x - xi;
                float dy = pcur.y - yi;
                float dz = pcur.z - zi;
                if (fmaxf(fmaxf(fabsf(dx), fabsf(dy)), fabsf(dz)) < PRADIUS) {
                    unsigned j = (unsigned)__float_as_int(pcur.w);
                    float d = __fadd_rn(
                        __fadd_rn(__fmul_rn(dx, dx), __fmul_rn(dy, dy)),
                        __fmul_rn(dz, dz));
                    unsigned long long ck =
                        ((unsigned long long)(unsigned)__float_as_int(d) << 32) | j;
                    int oct = ((dx > 0.0f) ? 4 : 0) |
                              ((dy > 0.0f) ? 2 : 0) |
                              ((dz > 0.0f) ? 1 : 0);
                    atomicMin(&s_key[qb][oct], ck);
                }
            }
            // rare tail: span longer than 16 candidates
            for (int k = kcur + 16; k < ecur; k += 16) {
                float4 p = srt[k];
                float dx = p.x - xi;
                float dy = p.y - yi;
                float dz = p.z - zi;
                if (fmaxf(fmaxf(fabsf(dx), fabsf(dy)), fabsf(dz)) < PRADIUS) {
                    unsigned j = (unsigned)__float_as_int(p.w);
                    float d = __fadd_rn(
                        __fadd_rn(__fmul_rn(dx, dx), __fmul_rn(dy, dy)),
                        __fmul_rn(dz, dz));
                    unsigned long long ck =
                        ((unsigned long long)(unsigned)__float_as_int(d) << 32) | j;
                    int oct = ((dx > 0.0f) ? 4 : 0) |
                              ((dy > 0.0f) ? 2 : 0) |
                              ((dz > 0.0f) ? 1 : 0);
                    atomicMin(&s_key[qb][oct], ck);
                }
            }

            // rotate pipeline
            sp   = spn;
            kcur = knxt; ecur = enxt; vcur = vnxt; pcur = pnxt;
        }
    }
    __syncthreads();

    // publish winners into s_jj (idx written per-query below)
    if (tid < QPB * 8) {
        s_jj[tid >> 3][tid & 7] =
            (int)(unsigned)(s_key[tid >> 3][tid & 7] & 0xFFFFFFFFull);
    }
    __syncthreads();

    // ---------------- gather: warp w owns sorted query (q0 + w) -----------
    const float4 mq = srt[q0 + w];
    const int    iw = __float_as_int(mq.w);      // original index -> out row
    const size_t row = (size_t)b * N + iw;

    if (lane < 8)
        idx_f[row * 8 + lane] = (float)s_jj[w][lane];

    // centered xyz: 24 values (lanes 0..23)
    if (lane < 24) {
        int o = lane / 3;
        int c = lane - o * 3;
        int jj = s_jj[w][o];
        float own = (c == 0) ? mq.x : (c == 1) ? mq.y : mq.z;
        float v = xb[3 * jj + c] - own;
        s_stage[w][o * FROW + c] = v;
        s_gx[w][lane] = v;
    }

    // features: 8 octants x 16 float4 = 128 vector loads, 4 dense iterations
    const float4* __restrict__ pb4 =
        (const float4*)(pts + (size_t)b * N * CFEAT);
    #pragma unroll
    for (int t0 = 0; t0 < 4; t0++) {
        int t  = lane + t0 * 32;     // 0..127
        int o  = t >> 4;
        int q  = t & 15;
        int jj = s_jj[w][o];
        float4 f4 = pb4[(size_t)jj * 16 + q];
        int base = o * FROW + 3 + q * 4;
        s_stage[w][base + 0] = f4.x;
        s_stage[w][base + 1] = f4.y;
        s_stage[w][base + 2] = f4.z;
        s_stage[w][base + 3] = f4.w;
    }
    __syncwarp();

    // write-out: 536 floats = 134 aligned float4 to the original row
    float4*       gpo = (float4*)(gp + row * GPROW);
    const float4* st4 = (const float4*)s_stage[w];
    #pragma unroll
    for (int f = lane; f < GPROW / 4; f += 32)
        gpo[f] = st4[f];
    if (lane < 6)
        ((float4*)(gxyz + row * 24))[lane] =
            ((const float4*)s_gx[w])[lane];
}

extern "C" void kernel_launch(void* const* d_in, const int* in_sizes, int n_in,
                              void* d_out, int out_size) {
    const float* xyz = (const float*)d_in[0];
    const float* pts = (const float*)d_in[1];
    float* out = (float*)d_out;

    int BN = in_sizes[0] / 3;       // B*N = 8192
    int B  = 2;
    int N  = BN / B;                // 4096

    size_t nG = (size_t)BN * 8;
    float* gxyz  = out;
    float* gp    = out + nG * 3;
    float* idx_f = out + nG * 3 + nG * (size_t)FROW;

    k_build<<<B, 1024>>>(xyz, N);

    // PDL launch of the dependent query kernel on the same (capture) stream.
    {
        cudaLaunchAttribute attrs[1];
        attrs[0].id = cudaLaunchAttributeProgrammaticStreamSerialization;
        attrs[0].val.programmaticStreamSerializationAllowed = 1;

        cudaLaunchConfig_t cfg = {};
        cfg.gridDim  = dim3((BN + QPB - 1) / QPB, 1, 1);
        cfg.blockDim = dim3(QPB * 32, 1, 1);
        cfg.dynamicSmemBytes = 0;
        cfg.stream = 0;                 // legacy default stream (captured)
        cfg.attrs = attrs;
        cfg.numAttrs = 1;

        cudaLaunchKernelEx(&cfg, k_query_gather,
                           xyz, pts, gxyz, gp, idx_f, B, N);
    }
}